// round 5
// baseline (speedup 1.0000x reference)
#include <cuda_runtime.h>
#include <math.h>

#define N_TOKENS 16384
#define D_MODEL  4096
#define NE       64
#define BM 64
#define BN 128
#define BK 32
#define APAD 36
#define WPAD 36
#define NCHUNK (D_MODEL / BK)
// smem: 2 A buffers (64*36) + 2 W buffers (128*36) floats
#define SMEM_FLOATS (2*BM*APAD + 2*BN*WPAD)
#define SMEM_BYTES  (SMEM_FLOATS * 4)

__device__ float g_load[NE];
__device__ float g_imp[NE];

__device__ __forceinline__ unsigned long long ffma2(unsigned long long a,
                                                    unsigned long long b,
                                                    unsigned long long c) {
    unsigned long long d;
    asm("fma.rn.f32x2 %0, %1, %2, %3;" : "=l"(d) : "l"(a), "l"(b), "l"(c));
    return d;
}

__device__ __forceinline__ float softplusf(float x) {
    return fmaxf(x, 0.0f) + log1pf(expf(-fabsf(x)));
}

__global__ void __launch_bounds__(64) init_kernel() {
    int t = threadIdx.x;
    if (t < NE) { g_load[t] = 0.0f; g_imp[t] = 0.0f; }
}

__global__ void __launch_bounds__(256) gate_kernel(
    const float* __restrict__ inp,
    const float* __restrict__ wgate,
    const float* __restrict__ wnoise,
    const float* __restrict__ noise,
    float* __restrict__ out)
{
    extern __shared__ float sm[];
    float* Abuf0 = sm;
    float* Abuf1 = sm + BM * APAD;
    float* Wbuf0 = sm + 2 * BM * APAD;
    float* Wbuf1 = Wbuf0 + BN * WPAD;

    const int tid = threadIdx.x;
    const int tx  = tid & 31;
    const int wid = tid >> 5;
    const int row0 = blockIdx.x * BM;

    // A staging: idx = tid + 256u -> k-quad = idx&7, row = idx>>3
    const int a_kq  = tid & 7;
    const int a_row = tid >> 3;   // 0..31, second iter +32

    unsigned long long acc[8][4];
#pragma unroll
    for (int r = 0; r < 8; ++r)
#pragma unroll
        for (int j = 0; j < 4; ++j) acc[r][j] = 0ULL;

    // ---- prologue: chunk 0 straight into buffer 0 ----
    {
        const float* ap = inp + (long long)row0 * D_MODEL;
#pragma unroll
        for (int u = 0; u < 2; ++u) {
            int row = a_row + 32 * u;
            float4 v = *(const float4*)(ap + (long long)row * D_MODEL + 4 * a_kq);
            *(float4*)(Abuf0 + row * APAD + 4 * a_kq) = v;
        }
#pragma unroll
        for (int u = 0; u < 4; ++u) {
            int idx = tid + 256 * u;
            int cq = idx & 15, kk = (idx >> 4) & 31, mat = idx >> 9;
            const float* src = mat ? wnoise : wgate;
            float4 v = *(const float4*)(src + kk * NE + 4 * cq);
            int c = 4 * cq + 64 * mat;
            float* d = Wbuf0 + kk;
            d[(c + 0) * WPAD] = v.x;
            d[(c + 1) * WPAD] = v.y;
            d[(c + 2) * WPAD] = v.z;
            d[(c + 3) * WPAD] = v.w;
        }
    }
    __syncthreads();

    float4 aR[2], wR[4];
    for (int ch = 0; ch < NCHUNK; ++ch) {
        float* Acur = (ch & 1) ? Abuf1 : Abuf0;
        float* Wcur = (ch & 1) ? Wbuf1 : Wbuf0;
        float* Anxt = (ch & 1) ? Abuf0 : Abuf1;
        float* Wnxt = (ch & 1) ? Wbuf0 : Wbuf1;
        const int k0n = (ch + 1) * BK;
        const bool more = (ch + 1 < NCHUNK);

        if (more) {
            const float* ap = inp + (long long)row0 * D_MODEL + k0n;
#pragma unroll
            for (int u = 0; u < 2; ++u) {
                int row = a_row + 32 * u;
                aR[u] = *(const float4*)(ap + (long long)row * D_MODEL + 4 * a_kq);
            }
#pragma unroll
            for (int u = 0; u < 4; ++u) {
                int idx = tid + 256 * u;
                int cq = idx & 15, kk = (idx >> 4) & 31, mat = idx >> 9;
                const float* src = mat ? wnoise : wgate;
                wR[u] = *(const float4*)(src + (long long)(k0n + kk) * NE + 4 * cq);
            }
        }

        // ---- compute on current buffers ----
        {
            const float* Ap = Acur + (wid * 8) * APAD;
            const float* Wp = Wcur + tx * WPAD;
#pragma unroll
            for (int k = 0; k < BK; k += 4) {
                ulonglong2 b[4];
#pragma unroll
                for (int j = 0; j < 4; ++j)
                    b[j] = *(const ulonglong2*)(Wp + (32 * j) * WPAD + k);
#pragma unroll
                for (int r = 0; r < 8; ++r) {
                    ulonglong2 a = *(const ulonglong2*)(Ap + r * APAD + k);
#pragma unroll
                    for (int j = 0; j < 4; ++j) {
                        acc[r][j] = ffma2(a.x, b[j].x, acc[r][j]);
                        acc[r][j] = ffma2(a.y, b[j].y, acc[r][j]);
                    }
                }
            }
        }

        if (more) {
#pragma unroll
            for (int u = 0; u < 2; ++u) {
                int row = a_row + 32 * u;
                *(float4*)(Anxt + row * APAD + 4 * a_kq) = aR[u];
            }
#pragma unroll
            for (int u = 0; u < 4; ++u) {
                int idx = tid + 256 * u;
                int cq = idx & 15, kk = (idx >> 4) & 31, mat = idx >> 9;
                int c = 4 * cq + 64 * mat;
                float* d = Wnxt + kk;
                d[(c + 0) * WPAD] = wR[u].x;
                d[(c + 1) * WPAD] = wR[u].y;
                d[(c + 2) * WPAD] = wR[u].z;
                d[(c + 3) * WPAD] = wR[u].w;
            }
        }
        __syncthreads();
    }

    // ---- dump logits to smem: L[64 tokens][128 cols] ----
    float* L = sm;
    float* s_red = sm + BM * BN;   // 128 floats of reduction space
#pragma unroll
    for (int r = 0; r < 8; ++r) {
#pragma unroll
        for (int j = 0; j < 4; ++j) {
            unsigned long long v = acc[r][j];
            float lo = __uint_as_float((unsigned)(v & 0xffffffffu));
            float hi = __uint_as_float((unsigned)(v >> 32));
            L[(wid * 8 + r) * BN + tx + 32 * j] = lo + hi;
        }
    }
    if (tid < 128) s_red[tid] = 0.0f;
    __syncthreads();

    // ---- epilogue: warp wid handles tokens [wid*8, wid*8+8) ----
    const unsigned FULL = 0xffffffffu;
    float loadacc0 = 0.f, loadacc1 = 0.f, impacc0 = 0.f, impacc1 = 0.f;

    for (int tt = 0; tt < 8; ++tt) {
        int t = wid * 8 + tt;
        long long tg = row0 + t;
        float clean0 = L[t * BN + tx];
        float clean1 = L[t * BN + tx + 32];
        float raw0 = L[t * BN + 64 + tx];
        float raw1 = L[t * BN + 96 + tx];
        float sd0 = softplusf(raw0) + 0.01f;
        float sd1 = softplusf(raw1) + 0.01f;
        float nz0 = clean0 + noise[tg * NE + tx] * sd0;
        float nz1 = clean1 + noise[tg * NE + tx + 32] * sd1;

        // top-1 (tie -> lowest index, matching jax.lax.top_k)
        float v1; int i1;
        if (nz0 >= nz1) { v1 = nz0; i1 = tx; } else { v1 = nz1; i1 = tx + 32; }
#pragma unroll
        for (int o = 16; o > 0; o >>= 1) {
            float vo = __shfl_xor_sync(FULL, v1, o);
            int   io = __shfl_xor_sync(FULL, i1, o);
            if (vo > v1 || (vo == v1 && io < i1)) { v1 = vo; i1 = io; }
        }
        // top-2 (exclude i1)
        float v2 = -INFINITY; int i2 = 1 << 30;
        if (i1 != tx) { v2 = nz0; i2 = tx; }
        if (i1 != tx + 32 && (nz1 > v2 || (nz1 == v2 && tx + 32 < i2))) { v2 = nz1; i2 = tx + 32; }
#pragma unroll
        for (int o = 16; o > 0; o >>= 1) {
            float vo = __shfl_xor_sync(FULL, v2, o);
            int   io = __shfl_xor_sync(FULL, i2, o);
            if (vo > v2 || (vo == v2 && io < i2)) { v2 = vo; i2 = io; }
        }
        // top-3 value only (exclude i1, i2)
        float v3 = -INFINITY; int i3 = 1 << 30;
        if (tx != i1 && tx != i2) { v3 = nz0; i3 = tx; }
        if (tx + 32 != i1 && tx + 32 != i2 &&
            (nz1 > v3 || (nz1 == v3 && tx + 32 < i3))) { v3 = nz1; i3 = tx + 32; }
#pragma unroll
        for (int o = 16; o > 0; o >>= 1) {
            float vo = __shfl_xor_sync(FULL, v3, o);
            int   io = __shfl_xor_sync(FULL, i3, o);
            if (vo > v3 || (vo == v3 && io < i3)) { v3 = vo; i3 = io; }
        }

        // gates = softmax(v1, v2)
        float e  = expf(v2 - v1);
        float g1 = 1.0f / (1.0f + e);
        float g2 = e / (1.0f + e);

        if (tx == 0) {
            out[2 * tg]     = (float)i1;
            out[2 * tg + 1] = (float)i2;
            out[2 * N_TOKENS + 2 * tg]     = g1;
            out[2 * N_TOKENS + 2 * tg + 1] = g2;
        }

        // load probabilities
        float th0 = (nz0 > v3) ? v3 : v2;
        float th1 = (nz1 > v3) ? v3 : v2;
        loadacc0 += normcdff((clean0 - th0) / sd0);
        loadacc1 += normcdff((clean1 - th1) / sd1);
        if (i1 == tx)      impacc0 += g1;
        if (i2 == tx)      impacc0 += g2;
        if (i1 == tx + 32) impacc1 += g1;
        if (i2 == tx + 32) impacc1 += g2;
    }

    atomicAdd(&s_red[tx],       loadacc0);
    atomicAdd(&s_red[tx + 32],  loadacc1);
    atomicAdd(&s_red[64 + tx],      impacc0);
    atomicAdd(&s_red[64 + tx + 32], impacc1);
    __syncthreads();
    if (tid < 64)        atomicAdd(&g_load[tid], s_red[tid]);
    else if (tid < 128)  atomicAdd(&g_imp[tid - 64], s_red[tid]);
}

__global__ void __launch_bounds__(32) loss_kernel(float* __restrict__ out) {
    int lane = threadIdx.x;
    const unsigned FULL = 0xffffffffu;
    float a0 = g_imp[lane],  a1 = g_imp[lane + 32];
    float b0 = g_load[lane], b1 = g_load[lane + 32];
    double si = (double)a0 + (double)a1;
    double sl = (double)b0 + (double)b1;
#pragma unroll
    for (int o = 16; o > 0; o >>= 1) {
        si += __shfl_xor_sync(FULL, si, o);
        sl += __shfl_xor_sync(FULL, sl, o);
    }
    double mi = si / 64.0, ml = sl / 64.0;
    double di = ((double)a0 - mi) * ((double)a0 - mi) + ((double)a1 - mi) * ((double)a1 - mi);
    double dl = ((double)b0 - ml) * ((double)b0 - ml) + ((double)b1 - ml) * ((double)b1 - ml);
#pragma unroll
    for (int o = 16; o > 0; o >>= 1) {
        di += __shfl_xor_sync(FULL, di, o);
        dl += __shfl_xor_sync(FULL, dl, o);
    }
    if (lane == 0) {
        double vi = di / 63.0, vl = dl / 63.0;
        double loss = vi / (mi * mi + 1e-10) + vl / (ml * ml + 1e-10);
        out[4 * N_TOKENS] = (float)loss;
    }
}

extern "C" void kernel_launch(void* const* d_in, const int* in_sizes, int n_in,
                              void* d_out, int out_size) {
    const float* inp = (const float*)d_in[0];
    const float* wg  = (const float*)d_in[1];
    const float* wn  = (const float*)d_in[2];
    const float* nz  = (const float*)d_in[3];
    float* out = (float*)d_out;

    cudaFuncSetAttribute(gate_kernel, cudaFuncAttributeMaxDynamicSharedMemorySize, SMEM_BYTES);

    init_kernel<<<1, 64>>>();
    gate_kernel<<<N_TOKENS / BM, 256, SMEM_BYTES>>>(inp, wg, wn, nz, out);
    loss_kernel<<<1, 32>>>(out);
}

// round 6
// speedup vs baseline: 1.3633x; 1.3633x over previous
#include <cuda_runtime.h>
#include <math.h>

#define N_TOKENS 16384
#define D_MODEL  4096
#define NE       64
#define BM 64
#define BN 128
#define BK 32
#define NCHUNK (D_MODEL / BK)
#define NBLK (N_TOKENS / BM)

// smem: A 64x32 floats (8KB) x2  +  W 128x32 floats (16KB) x2  = 48KB exactly
#define A_FLOATS (BM * BK)
#define W_FLOATS (BN * BK)
#define SMEM_FLOATS (2 * A_FLOATS + 2 * W_FLOATS)
#define SMEM_BYTES  (SMEM_FLOATS * 4)

// per-CTA partials: [blk][0..63]=load, [64..127]=importance
__device__ float g_part[NBLK][128];

__device__ __forceinline__ unsigned long long ffma2(unsigned long long a,
                                                    unsigned long long b,
                                                    unsigned long long c) {
    unsigned long long d;
    asm("fma.rn.f32x2 %0, %1, %2, %3;" : "=l"(d) : "l"(a), "l"(b), "l"(c));
    return d;
}

__device__ __forceinline__ float softplusf(float x) {
    return fmaxf(x, 0.0f) + log1pf(expf(-fabsf(x)));
}

__global__ void __launch_bounds__(256, 2) gate_kernel(
    const float* __restrict__ inp,
    const float* __restrict__ wgate,
    const float* __restrict__ wnoise,
    const float* __restrict__ noise,
    float* __restrict__ out)
{
    extern __shared__ float sm[];
    float* Abuf0 = sm;
    float* Abuf1 = sm + A_FLOATS;
    float* Wbuf0 = sm + 2 * A_FLOATS;
    float* Wbuf1 = Wbuf0 + W_FLOATS;

    const int tid = threadIdx.x;
    const int tx  = tid & 31;
    const int wid = tid >> 5;
    const int row0 = blockIdx.x * BM;

    // A staging: thread loads float4 (4 k) for rows a_row, a_row+32
    const int a_kq  = tid & 7;      // k-quad 0..7
    const int a_row = tid >> 3;     // 0..31

    // W staging: thread owns col w_c, k-groups w_kg0 + {0,2,4,6}
    const int w_c   = tid & 127;
    const int w_kg0 = tid >> 7;     // 0 or 1
    const int w_sw  = w_c & 7;      // swizzle key
    const float* wsrc = (w_c < 64) ? wgate : wnoise;
    const int w_col64 = w_c & 63;

    unsigned long long acc[8][4];
#pragma unroll
    for (int r = 0; r < 8; ++r)
#pragma unroll
        for (int j = 0; j < 4; ++j) acc[r][j] = 0ULL;

    // ---- prologue: chunk 0 into buffer 0 ----
    {
        const float* ap = inp + (long long)row0 * D_MODEL;
#pragma unroll
        for (int u = 0; u < 2; ++u) {
            int row = a_row + 32 * u;
            float4 v = *(const float4*)(ap + (long long)row * D_MODEL + 4 * a_kq);
            *(float4*)(Abuf0 + row * BK + 4 * a_kq) = v;
        }
#pragma unroll
        for (int i = 0; i < 4; ++i) {
            int kg = w_kg0 + 2 * i;                 // k-group 0..7
            const float* s = wsrc + (4 * kg) * NE + w_col64;
            float4 v;
            v.x = s[0]; v.y = s[NE]; v.z = s[2 * NE]; v.w = s[3 * NE];
            *(float4*)(Wbuf0 + w_c * BK + ((kg ^ w_sw) * 4)) = v;
        }
    }
    __syncthreads();

    float4 aR[2], wR[4];
    for (int ch = 0; ch < NCHUNK; ++ch) {
        float* Acur = (ch & 1) ? Abuf1 : Abuf0;
        float* Wcur = (ch & 1) ? Wbuf1 : Wbuf0;
        float* Anxt = (ch & 1) ? Abuf0 : Abuf1;
        float* Wnxt = (ch & 1) ? Wbuf0 : Wbuf1;
        const int k0n = (ch + 1) * BK;
        const bool more = (ch + 1 < NCHUNK);

        if (more) {
            const float* ap = inp + (long long)row0 * D_MODEL + k0n;
#pragma unroll
            for (int u = 0; u < 2; ++u) {
                int row = a_row + 32 * u;
                aR[u] = *(const float4*)(ap + (long long)row * D_MODEL + 4 * a_kq);
            }
#pragma unroll
            for (int i = 0; i < 4; ++i) {
                int kg = w_kg0 + 2 * i;
                const float* s = wsrc + (long long)(k0n + 4 * kg) * NE + w_col64;
                wR[i].x = s[0]; wR[i].y = s[NE]; wR[i].z = s[2 * NE]; wR[i].w = s[3 * NE];
            }
        }

        // ---- compute: 8 k-groups of 4 ----
        {
            const float* Ap = Acur + (wid * 8) * BK;
            const char*  Wp = (const char*)Wcur + tx * (BK * 4);
            const int xo = (tx & 7) * 16;
#pragma unroll
            for (int g = 0; g < 8; ++g) {
                const int off = (g * 16) ^ xo;
                ulonglong2 b[4];
#pragma unroll
                for (int j = 0; j < 4; ++j)
                    b[j] = *(const ulonglong2*)(Wp + j * (32 * BK * 4) + off);
#pragma unroll
                for (int r = 0; r < 8; ++r) {
                    ulonglong2 a = *(const ulonglong2*)(Ap + r * BK + 4 * g);
#pragma unroll
                    for (int j = 0; j < 4; ++j) {
                        acc[r][j] = ffma2(a.x, b[j].x, acc[r][j]);
                        acc[r][j] = ffma2(a.y, b[j].y, acc[r][j]);
                    }
                }
            }
        }

        if (more) {
#pragma unroll
            for (int u = 0; u < 2; ++u) {
                int row = a_row + 32 * u;
                *(float4*)(Anxt + row * BK + 4 * a_kq) = aR[u];
            }
#pragma unroll
            for (int i = 0; i < 4; ++i) {
                int kg = w_kg0 + 2 * i;
                *(float4*)(Wnxt + w_c * BK + ((kg ^ w_sw) * 4)) = wR[i];
            }
        }
        __syncthreads();
    }

    // ---- dump logits to smem: L[64 tokens][128 cols] ----
    float* L = sm;                    // 8192 floats (32KB), reuses GEMM smem
    float* s_red = sm + BM * BN;      // 128 floats
#pragma unroll
    for (int r = 0; r < 8; ++r) {
#pragma unroll
        for (int j = 0; j < 4; ++j) {
            unsigned long long v = acc[r][j];
            float lo = __uint_as_float((unsigned)(v & 0xffffffffu));
            float hi = __uint_as_float((unsigned)(v >> 32));
            L[(wid * 8 + r) * BN + tx + 32 * j] = lo + hi;
        }
    }
    if (tid < 128) s_red[tid] = 0.0f;
    __syncthreads();

    // ---- epilogue: warp wid handles tokens [wid*8, wid*8+8) ----
    const unsigned FULL = 0xffffffffu;
    float loadacc0 = 0.f, loadacc1 = 0.f, impacc0 = 0.f, impacc1 = 0.f;

    for (int tt = 0; tt < 8; ++tt) {
        int t = wid * 8 + tt;
        long long tg = row0 + t;
        float clean0 = L[t * BN + tx];
        float clean1 = L[t * BN + tx + 32];
        float raw0 = L[t * BN + 64 + tx];
        float raw1 = L[t * BN + 96 + tx];
        float sd0 = softplusf(raw0) + 0.01f;
        float sd1 = softplusf(raw1) + 0.01f;
        float nz0 = clean0 + noise[tg * NE + tx] * sd0;
        float nz1 = clean1 + noise[tg * NE + tx + 32] * sd1;

        // top-1 (tie -> lowest index, matching jax.lax.top_k)
        float v1; int i1;
        if (nz0 >= nz1) { v1 = nz0; i1 = tx; } else { v1 = nz1; i1 = tx + 32; }
#pragma unroll
        for (int o = 16; o > 0; o >>= 1) {
            float vo = __shfl_xor_sync(FULL, v1, o);
            int   io = __shfl_xor_sync(FULL, i1, o);
            if (vo > v1 || (vo == v1 && io < i1)) { v1 = vo; i1 = io; }
        }
        // top-2 (exclude i1)
        float v2 = -INFINITY; int i2 = 1 << 30;
        if (i1 != tx) { v2 = nz0; i2 = tx; }
        if (i1 != tx + 32 && (nz1 > v2 || (nz1 == v2 && tx + 32 < i2))) { v2 = nz1; i2 = tx + 32; }
#pragma unroll
        for (int o = 16; o > 0; o >>= 1) {
            float vo = __shfl_xor_sync(FULL, v2, o);
            int   io = __shfl_xor_sync(FULL, i2, o);
            if (vo > v2 || (vo == v2 && io < i2)) { v2 = vo; i2 = io; }
        }
        // top-3 value (exclude i1, i2)
        float v3 = -INFINITY; int i3 = 1 << 30;
        if (tx != i1 && tx != i2) { v3 = nz0; i3 = tx; }
        if (tx + 32 != i1 && tx + 32 != i2 &&
            (nz1 > v3 || (nz1 == v3 && tx + 32 < i3))) { v3 = nz1; i3 = tx + 32; }
#pragma unroll
        for (int o = 16; o > 0; o >>= 1) {
            float vo = __shfl_xor_sync(FULL, v3, o);
            int   io = __shfl_xor_sync(FULL, i3, o);
            if (vo > v3 || (vo == v3 && io < i3)) { v3 = vo; i3 = io; }
        }

        // gates = softmax(v1, v2)
        float e  = expf(v2 - v1);
        float g1 = 1.0f / (1.0f + e);
        float g2 = e / (1.0f + e);

        if (tx == 0) {
            out[2 * tg]     = (float)i1;
            out[2 * tg + 1] = (float)i2;
            out[2 * N_TOKENS + 2 * tg]     = g1;
            out[2 * N_TOKENS + 2 * tg + 1] = g2;
        }

        // load probabilities
        float th0 = (nz0 > v3) ? v3 : v2;
        float th1 = (nz1 > v3) ? v3 : v2;
        loadacc0 += normcdff((clean0 - th0) / sd0);
        loadacc1 += normcdff((clean1 - th1) / sd1);
        if (i1 == tx)      impacc0 += g1;
        if (i2 == tx)      impacc0 += g2;
        if (i1 == tx + 32) impacc1 += g1;
        if (i2 == tx + 32) impacc1 += g2;
    }

    atomicAdd(&s_red[tx],           loadacc0);
    atomicAdd(&s_red[tx + 32],      loadacc1);
    atomicAdd(&s_red[64 + tx],      impacc0);
    atomicAdd(&s_red[64 + tx + 32], impacc1);
    __syncthreads();
    if (tid < 128) g_part[blockIdx.x][tid] = s_red[tid];
}

__global__ void __launch_bounds__(128) loss_kernel(float* __restrict__ out) {
    int t = threadIdx.x;
    float s = 0.0f;
#pragma unroll 8
    for (int b = 0; b < NBLK; ++b) s += g_part[b][t];
    __shared__ float tot[128];
    tot[t] = s;
    __syncthreads();
    if (t < 32) {
        const unsigned FULL = 0xffffffffu;
        float b0 = tot[t],      b1 = tot[32 + t];   // load
        float a0 = tot[64 + t], a1 = tot[96 + t];   // importance
        double si = (double)a0 + (double)a1;
        double sl = (double)b0 + (double)b1;
#pragma unroll
        for (int o = 16; o > 0; o >>= 1) {
            si += __shfl_xor_sync(FULL, si, o);
            sl += __shfl_xor_sync(FULL, sl, o);
        }
        double mi = si / 64.0, ml = sl / 64.0;
        double di = ((double)a0 - mi) * ((double)a0 - mi) + ((double)a1 - mi) * ((double)a1 - mi);
        double dl = ((double)b0 - ml) * ((double)b0 - ml) + ((double)b1 - ml) * ((double)b1 - ml);
#pragma unroll
        for (int o = 16; o > 0; o >>= 1) {
            di += __shfl_xor_sync(FULL, di, o);
            dl += __shfl_xor_sync(FULL, dl, o);
        }
        if (t == 0) {
            double vi = di / 63.0, vl = dl / 63.0;
            double loss = vi / (mi * mi + 1e-10) + vl / (ml * ml + 1e-10);
            out[4 * N_TOKENS] = (float)loss;
        }
    }
}

extern "C" void kernel_launch(void* const* d_in, const int* in_sizes, int n_in,
                              void* d_out, int out_size) {
    const float* inp = (const float*)d_in[0];
    const float* wg  = (const float*)d_in[1];
    const float* wn  = (const float*)d_in[2];
    const float* nz  = (const float*)d_in[3];
    float* out = (float*)d_out;

    cudaFuncSetAttribute(gate_kernel, cudaFuncAttributeMaxDynamicSharedMemorySize, SMEM_BYTES);

    gate_kernel<<<NBLK, 256, SMEM_BYTES>>>(inp, wg, wn, nz, out);
    loss_kernel<<<1, 128>>>(out);
}